// round 4
// baseline (speedup 1.0000x reference)
#include <cuda_runtime.h>
#include <cuda_bf16.h>

// StaticGCN reduced form:
//   h = ones(N,128)  =>  h@W1 is one shared vector v1 = colsum(W1).
//   layer1: h1[c] = relu(s[c]*v1 + b1),  s[c] = sum_{e into c} norm[e] (incl self-loop)
//   layer2+meanpool: out = (sum_r Wt[r]*h1[r]) @ W2 / N + b2,
//                    Wt[r] = sum_{e from r} norm[e] (incl self-loop)
//   norm[e] = dinv[row]*attr*dinv[col],  dinv = rsqrt(deg),  deg[c] = 1 + sum attr into c.
//
// edge_index dtype is detected at runtime (JAX silently demotes int64->int32
// unless x64 is enabled): for int64 little-endian values < 2^17, every odd
// int32 word is 0. A detect kernel sets g_idx64; edge kernels branch uniformly.

#define MAXN 100000
#define F 128

__device__ float g_deg[MAXN];   // degree accumulator, then dinv in-place
__device__ float g_s[MAXN];     // per-dst norm sum
__device__ float g_wt[MAXN];    // per-src norm sum
__device__ float g_v1[F];       // colsum(W1)
__device__ float g_acc[F];      // sum_r Wt[r]*relu(s[r]*v1 + b1)
__device__ int   g_idx64;       // 1 if edge_index is int64, 0 if int32

// Detect index width: odd int32 words of an int64 index array (values < 2^17)
// are all zero; for int32 random indices they are essentially never all zero.
__global__ void k_detect(const int* __restrict__ w) {
    if (threadIdx.x == 0 && blockIdx.x == 0) {
        int any = 0;
        #pragma unroll 16
        for (int i = 1; i < 256; i += 2) any |= w[i];
        g_idx64 = (any == 0) ? 1 : 0;
    }
}

__global__ void k_zero(int n) {
    int i = blockIdx.x * blockDim.x + threadIdx.x;
    if (i < n) g_deg[i] = 0.0f;
    if (i < F) g_acc[i] = 0.0f;
}

// deg[c] += attr[e]  over real edges. idx = int32 view of edge_index base.
__global__ void k_deg(const int* __restrict__ idx,
                      const float* __restrict__ attr, int E, int n) {
    int e = blockIdx.x * blockDim.x + threadIdx.x;
    if (e >= E) return;
    int is64 = g_idx64;
    // col = edge_index[1] = elements [E, 2E)
    int c = is64 ? idx[2 * (E + e)] : idx[E + e];
    if ((unsigned)c < (unsigned)n)
        atomicAdd(&g_deg[c], attr[e]);
}

// dinv = rsqrt(deg + 1) (self-loop weight 1); seed s/wt with self-loop norm
__global__ void k_dinv(int n) {
    int i = blockIdx.x * blockDim.x + threadIdx.x;
    if (i < n) {
        float inv = rsqrtf(g_deg[i] + 1.0f);
        g_deg[i] = inv;
        float sn = inv * inv;   // self-loop norm = 1/deg_total
        g_s[i]  = sn;
        g_wt[i] = sn;
    }
}

// per real edge: norm = dinv[r]*attr*dinv[c]; s[c]+=norm; wt[r]+=norm
__global__ void k_edge(const int* __restrict__ idx,
                       const float* __restrict__ attr, int E, int n) {
    int e = blockIdx.x * blockDim.x + threadIdx.x;
    if (e >= E) return;
    int is64 = g_idx64;
    int r = is64 ? idx[2 * e]       : idx[e];
    int c = is64 ? idx[2 * (E + e)] : idx[E + e];
    if ((unsigned)r >= (unsigned)n || (unsigned)c >= (unsigned)n) return;
    float nr = g_deg[r] * attr[e] * g_deg[c];
    atomicAdd(&g_s[c],  nr);
    atomicAdd(&g_wt[r], nr);
}

// v1[j] = sum_i W1[i][j]
__global__ void k_v1(const float* __restrict__ W1) {
    int j = threadIdx.x;
    float v = 0.0f;
    #pragma unroll 8
    for (int i = 0; i < F; i++) v += W1[i * F + j];
    g_v1[j] = v;
}

// acc[j] = sum_r Wt[r] * relu(s[r]*v1[j] + b1[j])
__global__ void k_gather(const float* __restrict__ b1, int n) {
    int j = threadIdx.x;                 // 128 threads, one component each
    float v1 = g_v1[j];
    float bb = b1[j];
    float acc = 0.0f;
    for (int r = blockIdx.x; r < n; r += gridDim.x) {
        float sr = g_s[r];               // broadcast loads (L1/L2 hit)
        float wr = g_wt[r];
        acc += wr * fmaxf(fmaf(sr, v1, bb), 0.0f);
    }
    atomicAdd(&g_acc[j], acc);
}

// out[j] = (sum_k acc[k]*W2[k][j]) / n + b2[j]
__global__ void k_out(const float* __restrict__ W2,
                      const float* __restrict__ b2,
                      float* __restrict__ out, int n) {
    int j = threadIdx.x;
    float o = 0.0f;
    #pragma unroll 8
    for (int k = 0; k < F; k++) o = fmaf(g_acc[k], W2[k * F + j], o);
    out[j] = o / (float)n + b2[j];
}

extern "C" void kernel_launch(void* const* d_in, const int* in_sizes, int n_in,
                              void* d_out, int out_size) {
    // inputs (metadata order): x[N*128] f32, edge_index[2*E] int32-or-int64,
    // edge_attr[E] f32, W1[128*128] f32, b1[128] f32, W2[128*128] f32, b2[128] f32
    const int*   eidx = (const int*)d_in[1];     // int32 view (works for both widths)
    const float* attr = (const float*)d_in[2];
    const float* W1   = (const float*)d_in[3];
    const float* b1   = (const float*)d_in[4];
    const float* W2   = (const float*)d_in[5];
    const float* b2   = (const float*)d_in[6];
    float* out = (float*)d_out;

    int n = in_sizes[0] / F;     // 100000
    int E = in_sizes[2];         // 1600000

    int tb = 256;
    int nb_n = (n + tb - 1) / tb;
    int nb_e = (E + tb - 1) / tb;

    k_detect<<<1, 32>>>(eidx);
    k_zero<<<nb_n, tb>>>(n);
    k_deg<<<nb_e, tb>>>(eidx, attr, E, n);
    k_dinv<<<nb_n, tb>>>(n);
    k_edge<<<nb_e, tb>>>(eidx, attr, E, n);
    k_v1<<<1, F>>>(W1);
    k_gather<<<512, F>>>(b1, n);
    k_out<<<1, F>>>(W2, b2, out, n);
}

// round 5
// speedup vs baseline: 1.7108x; 1.7108x over previous
#include <cuda_runtime.h>
#include <cuda_bf16.h>

// StaticGCN fully-fused persistent kernel.
//
// Math reduction (h is overwritten with ones, so h@W1 == colsum(W1) =: v1 for
// every node):
//   deg[c]  = 1 + sum_{e into c} attr[e]           (self-loop weight 1)
//   dinv    = rsqrt(deg)
//   norm[e] = dinv[row]*attr[e]*dinv[col];  self-loop norm = dinv^2
//   s[c]    = sum_{e into c} norm[e]        (incl self)
//   wt[r]   = sum_{e from r} norm[e]        (incl self)
//   h1[r]   = relu(s[r]*v1 + b1)            (vector in j)
//   out[j]  = (sum_r wt[r]*h1[r]) @ W2 / n + b2
//
// One persistent kernel, 148 blocks x 512 threads (all co-resident on 152
// SMs), custom grid barrier between phases. Cross-phase table reads use
// __ldcg (L2) because there is no per-launch L1D flush inside one kernel.
// edge_index dtype (int32 vs int64) detected from the odd int32 words.

#define MAXN 100000
#define F 128
#define NB 148
#define NT 512
#define TOT (NB * NT)

__device__ float g_deg[MAXN];     // degree accum -> dinv in place
__device__ float g_s[MAXN];
__device__ float g_wt[MAXN];
__device__ float g_v1[F];
__device__ float g_acc[F];
__device__ int   g_idx64;
__device__ unsigned g_count = 0;  // barrier arrival counter (returns to 0)
__device__ unsigned g_gen   = 0;  // barrier generation (monotonic)

__device__ __forceinline__ void grid_bar(unsigned base, unsigned iter) {
    __syncthreads();
    if (threadIdx.x == 0) {
        __threadfence();                       // drain my stores to L2
        unsigned arrived = atomicAdd(&g_count, 1u);
        if (arrived == NB - 1) {
            g_count = 0;                       // safe: all NB arrived
            __threadfence();
            atomicAdd(&g_gen, 1u);
        } else {
            while (*(volatile unsigned*)&g_gen - base < iter) { }
            __threadfence();
        }
    }
    __syncthreads();
}

__global__ void __launch_bounds__(NT, 1) gcn_fused(
    const int* __restrict__ eidx,   // int32 view of edge_index
    const float* __restrict__ attr,
    const float* __restrict__ W1, const float* __restrict__ b1,
    const float* __restrict__ W2, const float* __restrict__ b2,
    float* __restrict__ out, int n, int E)
{
    __shared__ float sh_s[F];
    __shared__ float sh_w[F];
    __shared__ float sh_red[NT];
    __shared__ unsigned sh_base;

    const int tid  = threadIdx.x;
    const int bid  = blockIdx.x;
    const int gtid = bid * NT + tid;

    if (tid == 0) sh_base = *(volatile unsigned*)&g_gen;
    __syncthreads();
    const unsigned base = sh_base;

    // ---------------- Phase A: init + detect + v1 ----------------
    for (int i = gtid; i < n; i += TOT) g_deg[i] = 0.0f;
    if (bid == 0 && tid < F) { g_acc[tid] = 0.0f; out[tid] = b2[tid]; }
    if (bid == 1 && tid < F) {               // v1[j] = colsum(W1)[j]
        float v = 0.0f;
        #pragma unroll 8
        for (int i = 0; i < F; i++) v += W1[i * F + tid];
        g_v1[tid] = v;
    }
    if (bid == 2 && tid == 0) {              // int64 iff odd words all zero
        int any = 0;
        #pragma unroll 16
        for (int i = 1; i < 256; i += 2) any |= eidx[i];
        g_idx64 = (any == 0) ? 1 : 0;
    }
    grid_bar(base, 1);

    const int is64 = *(volatile int*)&g_idx64;
    const bool vec = (!is64) && ((E & 3) == 0);

    // ---------------- Phase B: deg[c] += attr[e] ----------------
    if (vec) {
        const int4*   c4 = (const int4*)(eidx + E);
        const float4* a4 = (const float4*)attr;
        const int nv = E >> 2;
        for (int i = gtid; i < nv; i += TOT) {
            int4 c = c4[i]; float4 a = a4[i];
            atomicAdd(&g_deg[c.x], a.x);
            atomicAdd(&g_deg[c.y], a.y);
            atomicAdd(&g_deg[c.z], a.z);
            atomicAdd(&g_deg[c.w], a.w);
        }
    } else {
        for (int e = gtid; e < E; e += TOT) {
            int c = is64 ? eidx[2 * (E + e)] : eidx[E + e];
            if ((unsigned)c < (unsigned)n) atomicAdd(&g_deg[c], attr[e]);
        }
    }
    grid_bar(base, 2);

    // ---------------- Phase C: dinv; seed s/wt with self-loop ----------------
    for (int i = gtid; i < n; i += TOT) {
        float inv = rsqrtf(__ldcg(&g_deg[i]) + 1.0f);
        g_deg[i] = inv;
        float sn = inv * inv;
        g_s[i]  = sn;
        g_wt[i] = sn;
    }
    grid_bar(base, 3);

    // ---------------- Phase D: per-edge norm scatter ----------------
    if (vec) {
        const int4*   r4 = (const int4*)eidx;
        const int4*   c4 = (const int4*)(eidx + E);
        const float4* a4 = (const float4*)attr;
        const int nv = E >> 2;
        for (int i = gtid; i < nv; i += TOT) {
            int4 r = r4[i]; int4 c = c4[i]; float4 a = a4[i];
            float n0 = __ldcg(&g_deg[r.x]) * a.x * __ldcg(&g_deg[c.x]);
            float n1 = __ldcg(&g_deg[r.y]) * a.y * __ldcg(&g_deg[c.y]);
            float n2 = __ldcg(&g_deg[r.z]) * a.z * __ldcg(&g_deg[c.z]);
            float n3 = __ldcg(&g_deg[r.w]) * a.w * __ldcg(&g_deg[c.w]);
            atomicAdd(&g_s[c.x], n0);  atomicAdd(&g_wt[r.x], n0);
            atomicAdd(&g_s[c.y], n1);  atomicAdd(&g_wt[r.y], n1);
            atomicAdd(&g_s[c.z], n2);  atomicAdd(&g_wt[r.z], n2);
            atomicAdd(&g_s[c.w], n3);  atomicAdd(&g_wt[r.w], n3);
        }
    } else {
        for (int e = gtid; e < E; e += TOT) {
            int r = is64 ? eidx[2 * e]       : eidx[e];
            int c = is64 ? eidx[2 * (E + e)] : eidx[E + e];
            if ((unsigned)r >= (unsigned)n || (unsigned)c >= (unsigned)n) continue;
            float nr = __ldcg(&g_deg[r]) * attr[e] * __ldcg(&g_deg[c]);
            atomicAdd(&g_s[c],  nr);
            atomicAdd(&g_wt[r], nr);
        }
    }
    grid_bar(base, 4);

    // ------- Phase E: acc[j] = sum_r wt[r]*relu(s[r]*v1[j]+b1[j]) -------
    {
        const int j = tid & (F - 1);
        const int half = tid >> 7;              // 0..3
        const float v1j = __ldcg(&g_v1[j]);
        const float b1j = b1[j];
        float accj = 0.0f;
        const int nchunk = (n + F - 1) / F;
        for (int cid = bid; cid < nchunk; cid += NB) {
            int rb = cid * F;
            if (tid < F) {
                int r = rb + tid;
                sh_s[tid] = (r < n) ? __ldcg(&g_s[r]) : 0.0f;
            } else if (tid < 2 * F) {
                int r = rb + tid - F;
                sh_w[tid - F] = (r < n) ? __ldcg(&g_wt[r]) : 0.0f;
            }
            __syncthreads();
            #pragma unroll 8
            for (int rr = half; rr < F; rr += 4)
                accj += sh_w[rr] * fmaxf(fmaf(sh_s[rr], v1j, b1j), 0.0f);
            __syncthreads();
        }
        sh_red[tid] = accj;
        __syncthreads();
        if (tid < F)
            atomicAdd(&g_acc[tid],
                      sh_red[tid] + sh_red[tid + F] +
                      sh_red[tid + 2 * F] + sh_red[tid + 3 * F]);
    }
    grid_bar(base, 5);

    // ---------------- Phase F: out[j] += acc @ W2 / n ----------------
    if (bid < F && tid < F) {
        float a = __ldcg(&g_acc[bid]) * (1.0f / (float)n);
        atomicAdd(&out[tid], a * W2[bid * F + tid]);
    }
}

extern "C" void kernel_launch(void* const* d_in, const int* in_sizes, int n_in,
                              void* d_out, int out_size) {
    // inputs: x[N*128] f32, edge_index[2*E] int32-or-int64, edge_attr[E] f32,
    //         W1[128*128], b1[128], W2[128*128], b2[128]
    const int*   eidx = (const int*)d_in[1];
    const float* attr = (const float*)d_in[2];
    const float* W1   = (const float*)d_in[3];
    const float* b1   = (const float*)d_in[4];
    const float* W2   = (const float*)d_in[5];
    const float* b2   = (const float*)d_in[6];
    float* out = (float*)d_out;

    int n = in_sizes[0] / F;   // 100000
    int E = in_sizes[2];       // 1600000

    gcn_fused<<<NB, NT>>>(eidx, attr, W1, b1, W2, b2, out, n, E);
}